// round 5
// baseline (speedup 1.0000x reference)
#include <cuda_runtime.h>
#include <cuda_bf16.h>
#include <cstdint>

#define MAXN 100000
#define MAXE 1600000
#define F 64

#define SCAN_TPB 256
#define SCAN_EPT 8
#define SCAN_EPB (SCAN_TPB * SCAN_EPT)   // 2048
#define MAX_NB 1024                      // supports n up to 2M

// -------- scratch (static device globals; no allocation allowed) ----------
__device__ float g_agg[(size_t)MAXN * F];
__device__ float g_h1[(size_t)MAXN * F];
__device__ int   g_deg[MAXN];
__device__ int   g_rowstart[MAXN];
__device__ int   g_cursor[MAXN];
__device__ int   g_eidx[MAXE];
__device__ int   g_bsum[MAX_NB];
__device__ int   g_is64;

// --------------------- zero deg + edge dtype detection ---------------------
// Reference claims int64 edges, but JAX without x64 silently emits int32.
// Detect on device: if the first 64 slots interpreted as int64 all lie in
// [0, n), the buffer is int64 (random int32 pairs >= 2^32 almost surely).
__global__ void k_zero_detect(const void* __restrict__ eiv, int n) {
    int i = blockIdx.x * blockDim.x + threadIdx.x;
    if (i < n) g_deg[i] = 0;
    if (i == 0) {
        const long long* p = (const long long*)eiv;
        int ok = 1;
        #pragma unroll 1
        for (int j = 0; j < 64; j++) {
            long long v = p[j];
            if (v < 0 || v >= (long long)n) { ok = 0; break; }
        }
        g_is64 = ok;
    }
}

__device__ __forceinline__ int load_edge(const void* eiv, size_t idx, int n) {
    int v;
    if (g_is64) v = (int)((const long long*)eiv)[idx];
    else        v = ((const int*)eiv)[idx];
    return min(max(v, 0), n - 1);   // never traps; wrong guess -> visible rel_err
}

// --------------------------- CSR build ------------------------------------
__global__ void k_count(const void* __restrict__ eiv, int E, int n) {
    int e = blockIdx.x * blockDim.x + threadIdx.x;
    if (e < E) {
        int d = load_edge(eiv, (size_t)E + e, n);
        atomicAdd(&g_deg[d], 1);
    }
}

// ---- hierarchical exclusive scan of g_deg -> g_rowstart/g_cursor ----------
__global__ void k_scan_bsum(int n) {
    int tid = threadIdx.x, b = blockIdx.x;
    int base = b * SCAN_EPB + tid * SCAN_EPT;
    int s = 0;
    #pragma unroll
    for (int i = 0; i < SCAN_EPT; i++) {
        int id = base + i;
        int idc = id < n ? id : (n - 1);
        int v = g_deg[idc];
        s += (id < n) ? v : 0;
    }
    // warp reduce
    #pragma unroll
    for (int off = 16; off > 0; off >>= 1)
        s += __shfl_down_sync(0xffffffffu, s, off);
    __shared__ int wsum[SCAN_TPB / 32];
    if ((tid & 31) == 0) wsum[tid >> 5] = s;
    __syncthreads();
    if (tid < 32) {
        int v = (tid < SCAN_TPB / 32) ? wsum[tid] : 0;
        #pragma unroll
        for (int off = 16; off > 0; off >>= 1)
            v += __shfl_down_sync(0xffffffffu, v, off);
        if (tid == 0) g_bsum[b] = v;
    }
}

// single warp: exclusive scan of nb block sums in place
__global__ void k_scan_bscan(int nb) {
    int lane = threadIdx.x;
    int carry = 0;
    for (int base = 0; base < nb; base += 32) {
        int id = base + lane;
        int v = (id < nb) ? g_bsum[id] : 0;
        int incl = v;
        #pragma unroll
        for (int off = 1; off < 32; off <<= 1) {
            int t = __shfl_up_sync(0xffffffffu, incl, off);
            if (lane >= off) incl += t;
        }
        if (id < nb) g_bsum[id] = carry + incl - v;   // exclusive
        carry += __shfl_sync(0xffffffffu, incl, 31);
    }
}

__global__ void k_scan_final(int n) {
    int tid = threadIdx.x, b = blockIdx.x;
    int lane = tid & 31, wid = tid >> 5;
    int base = b * SCAN_EPB + tid * SCAN_EPT;
    int v[SCAN_EPT];
    int tot = 0;
    #pragma unroll
    for (int i = 0; i < SCAN_EPT; i++) {
        int id = base + i;
        int idc = id < n ? id : (n - 1);
        int val = g_deg[idc];
        v[i] = (id < n) ? val : 0;
        tot += v[i];
    }
    // warp inclusive scan of thread totals
    int incl = tot;
    #pragma unroll
    for (int off = 1; off < 32; off <<= 1) {
        int t = __shfl_up_sync(0xffffffffu, incl, off);
        if (lane >= off) incl += t;
    }
    __shared__ int wtot[SCAN_TPB / 32];
    if (lane == 31) wtot[wid] = incl;
    __syncthreads();
    if (tid < 32) {
        int w = (tid < SCAN_TPB / 32) ? wtot[tid] : 0;
        int wincl = w;
        #pragma unroll
        for (int off = 1; off < 32; off <<= 1) {
            int t = __shfl_up_sync(0xffffffffu, wincl, off);
            if (tid >= off) wincl += t;
        }
        if (tid < SCAN_TPB / 32) wtot[tid] = wincl - w;   // exclusive warp offsets
    }
    __syncthreads();
    int run = g_bsum[b] + wtot[wid] + (incl - tot);   // exclusive prefix for elem 0
    #pragma unroll
    for (int i = 0; i < SCAN_EPT; i++) {
        int id = base + i;
        if (id < n) { g_rowstart[id] = run; g_cursor[id] = run; }
        run += v[i];
    }
}

__global__ void k_fill(const void* __restrict__ eiv, int E, int n) {
    int e = blockIdx.x * blockDim.x + threadIdx.x;
    if (e < E) {
        int d = load_edge(eiv, (size_t)E + e, n);
        int s = load_edge(eiv, (size_t)e, n);
        int pos = atomicAdd(&g_cursor[d], 1);
        if (pos < MAXE) g_eidx[pos] = s;
    }
}

// ------------------------ mean aggregation (gather-side) -------------------
// one warp per node; each lane owns one float2 (features 2*lane, 2*lane+1)
__device__ __forceinline__ void agg_body(const float* __restrict__ feat, int n) {
    int w = (blockIdx.x * blockDim.x + threadIdx.x) >> 5;
    int lane = threadIdx.x & 31;
    if (w >= n) return;
    int s = g_rowstart[w];
    int d = g_deg[w];
    float2 acc = make_float2(0.f, 0.f);
    const float2* f2 = (const float2*)feat;
    int i = 0;
    for (; i + 1 < d; i += 2) {
        int s0 = g_eidx[s + i];
        int s1 = g_eidx[s + i + 1];
        float2 a = f2[(size_t)s0 * 32 + lane];
        float2 b = f2[(size_t)s1 * 32 + lane];
        acc.x += a.x + b.x;
        acc.y += a.y + b.y;
    }
    if (i < d) {
        int s0 = g_eidx[s + i];
        float2 a = f2[(size_t)s0 * 32 + lane];
        acc.x += a.x; acc.y += a.y;
    }
    float inv = 1.0f / (float)max(d, 1);
    acc.x *= inv; acc.y *= inv;
    ((float2*)g_agg)[(size_t)w * 32 + lane] = acc;
}

__global__ void k_agg_x(const float* __restrict__ x, int n)  { agg_body(x, n); }
__global__ void k_agg_h1(int n)                              { agg_body(g_h1, n); }

// ------------------------ fused dual-GEMM + bias + ReLU --------------------
// 64-row tile per block, 256 threads, 4x4 microtile per thread.
__global__ void k_gemm_relu(const float* __restrict__ A0, const float* __restrict__ W0,
                            const float* __restrict__ W1,
                            const float* __restrict__ bias, int n)
{
    __shared__ __align__(16) float As[64][68];   // [k][row]
    __shared__ __align__(16) float Ws[64][64];   // [k][col]
    int tid = threadIdx.x;
    int row0 = blockIdx.x * 64;
    int tx = tid & 15, ty = tid >> 4;
    int r0 = ty * 4, c0 = tx * 4;
    float acc[4][4] = {};

    #pragma unroll
    for (int pass = 0; pass < 2; pass++) {
        const float* A = pass ? (const float*)g_agg : A0;
        const float* W = pass ? W1 : W0;
        __syncthreads();
        {
            int r  = tid >> 2;
            int kc = (tid & 3) * 16;
            int gr = row0 + r;
            int grc = gr < n ? gr : (n - 1);   // clamp: always-valid address
            const float4* a4 = (const float4*)(A + (size_t)grc * 64 + kc);
            #pragma unroll
            for (int i = 0; i < 4; i++) {
                float4 v = a4[i];
                int k = kc + i * 4;
                As[k + 0][r] = v.x; As[k + 1][r] = v.y;
                As[k + 2][r] = v.z; As[k + 3][r] = v.w;
            }
            int kk = tid >> 2;
            int jc = (tid & 3) * 16;
            const float4* w4 = (const float4*)(W + kk * 64 + jc);
            float4* ws4 = (float4*)(&Ws[kk][jc]);
            #pragma unroll
            for (int i = 0; i < 4; i++) ws4[i] = w4[i];
        }
        __syncthreads();
        #pragma unroll 8
        for (int k = 0; k < 64; k++) {
            float4 av = *(const float4*)(&As[k][r0]);
            float4 wv = *(const float4*)(&Ws[k][c0]);
            float a[4] = {av.x, av.y, av.z, av.w};
            float w[4] = {wv.x, wv.y, wv.z, wv.w};
            #pragma unroll
            for (int i = 0; i < 4; i++)
                #pragma unroll
                for (int j = 0; j < 4; j++)
                    acc[i][j] += a[i] * w[j];
        }
    }
    float4 bv = *(const float4*)(bias + c0);
    float bb[4] = {bv.x, bv.y, bv.z, bv.w};
    #pragma unroll
    for (int i = 0; i < 4; i++) {
        int gr = row0 + r0 + i;
        if (gr < n) {
            float4 o;
            o.x = fmaxf(acc[i][0] + bb[0], 0.f);
            o.y = fmaxf(acc[i][1] + bb[1], 0.f);
            o.z = fmaxf(acc[i][2] + bb[2], 0.f);
            o.w = fmaxf(acc[i][3] + bb[3], 0.f);
            *(float4*)(g_h1 + (size_t)gr * 64 + c0) = o;
        }
    }
}

// layer-2 variant: A0 = g_h1, A1 = g_agg; h2 stays in shared; fused 64->2 head.
__global__ void k_gemm_relu_final(const float* __restrict__ W0,
                                  const float* __restrict__ W1,
                                  const float* __restrict__ bias,
                                  const float* __restrict__ Wlin, const float* __restrict__ blin,
                                  float* __restrict__ out, int n)
{
    __shared__ __align__(16) float As[64][68];   // [k][row]; reused as Hs[c][row]
    __shared__ __align__(16) float Ws[64][64];
    __shared__ float Wls[128];
    __shared__ float bls[2];
    int tid = threadIdx.x;
    int row0 = blockIdx.x * 64;
    int tx = tid & 15, ty = tid >> 4;
    int r0 = ty * 4, c0 = tx * 4;
    float acc[4][4] = {};

    if (tid < 128) Wls[tid] = Wlin[tid];
    if (tid < 2)   bls[tid] = blin[tid];

    #pragma unroll
    for (int pass = 0; pass < 2; pass++) {
        const float* A = pass ? (const float*)g_agg : (const float*)g_h1;
        const float* W = pass ? W1 : W0;
        __syncthreads();
        {
            int r  = tid >> 2;
            int kc = (tid & 3) * 16;
            int gr = row0 + r;
            int grc = gr < n ? gr : (n - 1);
            const float4* a4 = (const float4*)(A + (size_t)grc * 64 + kc);
            #pragma unroll
            for (int i = 0; i < 4; i++) {
                float4 v = a4[i];
                int k = kc + i * 4;
                As[k + 0][r] = v.x; As[k + 1][r] = v.y;
                As[k + 2][r] = v.z; As[k + 3][r] = v.w;
            }
            int kk = tid >> 2;
            int jc = (tid & 3) * 16;
            const float4* w4 = (const float4*)(W + kk * 64 + jc);
            float4* ws4 = (float4*)(&Ws[kk][jc]);
            #pragma unroll
            for (int i = 0; i < 4; i++) ws4[i] = w4[i];
        }
        __syncthreads();
        #pragma unroll 8
        for (int k = 0; k < 64; k++) {
            float4 av = *(const float4*)(&As[k][r0]);
            float4 wv = *(const float4*)(&Ws[k][c0]);
            float a[4] = {av.x, av.y, av.z, av.w};
            float w[4] = {wv.x, wv.y, wv.z, wv.w};
            #pragma unroll
            for (int i = 0; i < 4; i++)
                #pragma unroll
                for (int j = 0; j < 4; j++)
                    acc[i][j] += a[i] * w[j];
        }
    }
    float4 bv = *(const float4*)(bias + c0);
    float bb[4] = {bv.x, bv.y, bv.z, bv.w};
    __syncthreads();
    #pragma unroll
    for (int i = 0; i < 4; i++)
        #pragma unroll
        for (int j = 0; j < 4; j++)
            As[c0 + j][r0 + i] = fmaxf(acc[i][j] + bb[j], 0.f);
    __syncthreads();
    if (tid < 128) {
        int r = tid >> 1, j = tid & 1;
        int gr = row0 + r;
        if (gr < n) {
            float s = bls[j];
            #pragma unroll 8
            for (int c = 0; c < 64; c++)
                s += As[c][r] * Wls[c * 2 + j];
            out[(size_t)gr * 2 + j] = s;
        }
    }
}

// ------------------------------ launch -------------------------------------
extern "C" void kernel_launch(void* const* d_in, const int* in_sizes, int n_in,
                              void* d_out, int out_size)
{
    const float* x      = (const float*)d_in[0];
    const void*  ei     = d_in[1];                 // int64 OR int32, detected on device
    const float* W1_agg = (const float*)d_in[2];
    const float* W1_root= (const float*)d_in[3];
    const float* b1     = (const float*)d_in[4];
    const float* W2_agg = (const float*)d_in[5];
    const float* W2_root= (const float*)d_in[6];
    const float* b2     = (const float*)d_in[7];
    const float* W_lin  = (const float*)d_in[8];
    const float* b_lin  = (const float*)d_in[9];
    float*       out    = (float*)d_out;

    int n = in_sizes[0] / F;       // 100000
    int E = in_sizes[1] / 2;       // 1600000
    int nb = (n + SCAN_EPB - 1) / SCAN_EPB;   // scan blocks (49)

    // CSR build (reused by both layers)
    k_zero_detect<<<(n + 255) / 256, 256>>>(ei, n);
    k_count<<<(E + 255) / 256, 256>>>(ei, E, n);
    k_scan_bsum<<<nb, SCAN_TPB>>>(n);
    k_scan_bscan<<<1, 32>>>(nb);
    k_scan_final<<<nb, SCAN_TPB>>>(n);
    k_fill<<<(E + 255) / 256, 256>>>(ei, E, n);

    int agg_blocks = (n * 32 + 255) / 256;
    int gemm_blocks = (n + 63) / 64;

    // layer 1: agg(x) -> g_agg; h1 = relu(x@W1_root + agg@W1_agg + b1) -> g_h1
    k_agg_x<<<agg_blocks, 256>>>(x, n);
    k_gemm_relu<<<gemm_blocks, 256>>>(x, W1_root, W1_agg, b1, n);
    // layer 2 + fused output head
    k_agg_h1<<<agg_blocks, 256>>>(n);
    k_gemm_relu_final<<<gemm_blocks, 256>>>(W2_root, W2_agg, b2, W_lin, b_lin, out, n);
}

// round 6
// speedup vs baseline: 1.5200x; 1.5200x over previous
#include <cuda_runtime.h>
#include <cuda_bf16.h>
#include <cstdint>

#define MAXN 100000
#define MAXE 1600000
#define F 64

#define SCAN_TPB 256
#define SCAN_EPT 8
#define SCAN_EPB (SCAN_TPB * SCAN_EPT)   // 2048
#define MAX_NB 1024

#define AS_STRIDE 68
#define WS_STRIDE 72
#define GEMM_SMEM ((2 * 64 * AS_STRIDE + 2 * 64 * WS_STRIDE) * 4)  // 71680 B

// -------- scratch (static device globals; no allocation allowed) ----------
__device__ float g_agg[(size_t)MAXN * F];
__device__ float g_h1[(size_t)MAXN * F];
__device__ int   g_deg[MAXN];
__device__ int   g_rowstart[MAXN];
__device__ int   g_cursor[MAXN];
__device__ int   g_eidx[MAXE];
__device__ int   g_bsum[MAX_NB];
__device__ int   g_is64;

// --------------------- zero deg + edge dtype detection ---------------------
__global__ void k_zero_detect(const void* __restrict__ eiv, int n) {
    int i = blockIdx.x * blockDim.x + threadIdx.x;
    if (i < n) g_deg[i] = 0;
    if (i == 0) {
        const long long* p = (const long long*)eiv;
        int ok = 1;
        #pragma unroll 1
        for (int j = 0; j < 64; j++) {
            long long v = p[j];
            if (v < 0 || v >= (long long)n) { ok = 0; break; }
        }
        g_is64 = ok;
    }
}

__device__ __forceinline__ int load_edge(const void* eiv, size_t idx, int n) {
    int v;
    if (g_is64) v = (int)((const long long*)eiv)[idx];
    else        v = ((const int*)eiv)[idx];
    return min(max(v, 0), n - 1);
}

// --------------------------- CSR build ------------------------------------
__global__ void k_count(const void* __restrict__ eiv, int E, int n) {
    int e = blockIdx.x * blockDim.x + threadIdx.x;
    if (e < E) {
        int d = load_edge(eiv, (size_t)E + e, n);
        atomicAdd(&g_deg[d], 1);
    }
}

__global__ void k_scan_bsum(int n) {
    int tid = threadIdx.x, b = blockIdx.x;
    int base = b * SCAN_EPB + tid * SCAN_EPT;
    int s = 0;
    #pragma unroll
    for (int i = 0; i < SCAN_EPT; i++) {
        int id = base + i;
        int idc = id < n ? id : (n - 1);
        int v = g_deg[idc];
        s += (id < n) ? v : 0;
    }
    #pragma unroll
    for (int off = 16; off > 0; off >>= 1)
        s += __shfl_down_sync(0xffffffffu, s, off);
    __shared__ int wsum[SCAN_TPB / 32];
    if ((tid & 31) == 0) wsum[tid >> 5] = s;
    __syncthreads();
    if (tid < 32) {
        int v = (tid < SCAN_TPB / 32) ? wsum[tid] : 0;
        #pragma unroll
        for (int off = 16; off > 0; off >>= 1)
            v += __shfl_down_sync(0xffffffffu, v, off);
        if (tid == 0) g_bsum[b] = v;
    }
}

__global__ void k_scan_bscan(int nb) {
    int lane = threadIdx.x;
    int carry = 0;
    for (int base = 0; base < nb; base += 32) {
        int id = base + lane;
        int v = (id < nb) ? g_bsum[id] : 0;
        int incl = v;
        #pragma unroll
        for (int off = 1; off < 32; off <<= 1) {
            int t = __shfl_up_sync(0xffffffffu, incl, off);
            if (lane >= off) incl += t;
        }
        if (id < nb) g_bsum[id] = carry + incl - v;
        carry += __shfl_sync(0xffffffffu, incl, 31);
    }
}

__global__ void k_scan_final(int n) {
    int tid = threadIdx.x, b = blockIdx.x;
    int lane = tid & 31, wid = tid >> 5;
    int base = b * SCAN_EPB + tid * SCAN_EPT;
    int v[SCAN_EPT];
    int tot = 0;
    #pragma unroll
    for (int i = 0; i < SCAN_EPT; i++) {
        int id = base + i;
        int idc = id < n ? id : (n - 1);
        int val = g_deg[idc];
        v[i] = (id < n) ? val : 0;
        tot += v[i];
    }
    int incl = tot;
    #pragma unroll
    for (int off = 1; off < 32; off <<= 1) {
        int t = __shfl_up_sync(0xffffffffu, incl, off);
        if (lane >= off) incl += t;
    }
    __shared__ int wtot[SCAN_TPB / 32];
    if (lane == 31) wtot[wid] = incl;
    __syncthreads();
    if (tid < 32) {
        int w = (tid < SCAN_TPB / 32) ? wtot[tid] : 0;
        int wincl = w;
        #pragma unroll
        for (int off = 1; off < 32; off <<= 1) {
            int t = __shfl_up_sync(0xffffffffu, wincl, off);
            if (tid >= off) wincl += t;
        }
        if (tid < SCAN_TPB / 32) wtot[tid] = wincl - w;
    }
    __syncthreads();
    int run = g_bsum[b] + wtot[wid] + (incl - tot);
    #pragma unroll
    for (int i = 0; i < SCAN_EPT; i++) {
        int id = base + i;
        if (id < n) { g_rowstart[id] = run; g_cursor[id] = run; }
        run += v[i];
    }
}

__global__ void k_fill(const void* __restrict__ eiv, int E, int n) {
    int e = blockIdx.x * blockDim.x + threadIdx.x;
    if (e < E) {
        int d = load_edge(eiv, (size_t)E + e, n);
        int s = load_edge(eiv, (size_t)e, n);
        int pos = atomicAdd(&g_cursor[d], 1);
        if (pos < MAXE) g_eidx[pos] = s;
    }
}

// ------------------------ mean aggregation (gather-side) -------------------
__device__ __forceinline__ void agg_body(const float* __restrict__ feat, int n) {
    int w = (blockIdx.x * blockDim.x + threadIdx.x) >> 5;
    int lane = threadIdx.x & 31;
    if (w >= n) return;
    int s = g_rowstart[w];
    int d = g_deg[w];
    float2 acc = make_float2(0.f, 0.f);
    const float2* f2 = (const float2*)feat;
    int i = 0;
    for (; i + 3 < d; i += 4) {
        int s0 = g_eidx[s + i];
        int s1 = g_eidx[s + i + 1];
        int s2 = g_eidx[s + i + 2];
        int s3 = g_eidx[s + i + 3];
        float2 a = f2[(size_t)s0 * 32 + lane];
        float2 b = f2[(size_t)s1 * 32 + lane];
        float2 c = f2[(size_t)s2 * 32 + lane];
        float2 e = f2[(size_t)s3 * 32 + lane];
        acc.x += (a.x + b.x) + (c.x + e.x);
        acc.y += (a.y + b.y) + (c.y + e.y);
    }
    for (; i < d; i++) {
        int s0 = g_eidx[s + i];
        float2 a = f2[(size_t)s0 * 32 + lane];
        acc.x += a.x; acc.y += a.y;
    }
    float inv = 1.0f / (float)max(d, 1);
    acc.x *= inv; acc.y *= inv;
    ((float2*)g_agg)[(size_t)w * 32 + lane] = acc;
}

__global__ void k_agg_x(const float* __restrict__ x, int n)  { agg_body(x, n); }
__global__ void k_agg_h1(int n)                              { agg_body(g_h1, n); }

// ------------------------ tensor-core GEMM (3xTF32) ------------------------
__device__ __forceinline__ uint32_t f2tf32(float x) {
    uint32_t r;
    asm("cvt.rna.tf32.f32 %0, %1;" : "=r"(r) : "f"(x));
    return r;
}

__device__ __forceinline__ void mma_tf32(float* d,
    uint32_t a0, uint32_t a1, uint32_t a2, uint32_t a3,
    uint32_t b0, uint32_t b1)
{
    asm volatile(
        "mma.sync.aligned.m16n8k8.row.col.f32.tf32.tf32.f32 "
        "{%0,%1,%2,%3}, {%4,%5,%6,%7}, {%8,%9}, {%0,%1,%2,%3};"
        : "+f"(d[0]), "+f"(d[1]), "+f"(d[2]), "+f"(d[3])
        : "r"(a0), "r"(a1), "r"(a2), "r"(a3), "r"(b0), "r"(b1));
}

extern __shared__ uint32_t dyn_smem[];

// Shared mainloop: acc[nt][4] = A0@W0 + g_agg@W1 for this block's 64-row tile.
// Warp layout: 8 warps -> 4 row-tiles(16) x 2 col-tiles(32); ntile = 4 x n8.
__device__ __forceinline__ void gemm_mainloop(
    const float* __restrict__ A0, const float* __restrict__ W0,
    const float* __restrict__ W1, int n, float acc[4][4])
{
    uint32_t* As_hi = dyn_smem;
    uint32_t* As_lo = As_hi + 64 * AS_STRIDE;
    uint32_t* Ws_hi = As_lo + 64 * AS_STRIDE;
    uint32_t* Ws_lo = Ws_hi + 64 * WS_STRIDE;

    int tid = threadIdx.x, lane = tid & 31, wid = tid >> 5;
    int row0 = blockIdx.x * 64;
    int rbase = (wid >> 1) * 16, nbase0 = (wid & 1) * 32;
    int g = lane >> 2, t = lane & 3;

    #pragma unroll
    for (int pass = 0; pass < 2; pass++) {
        const float* A = pass ? (const float*)g_agg : A0;
        const float* W = pass ? W1 : (const float*)W0;
        __syncthreads();
        {
            int r = tid >> 2, kc = (tid & 3) * 16;
            int gr = row0 + r;
            int grc = gr < n ? gr : (n - 1);
            const float4* a4 = (const float4*)(A + (size_t)grc * 64 + kc);
            #pragma unroll
            for (int i = 0; i < 4; i++) {
                float4 v = a4[i];
                float vv[4] = {v.x, v.y, v.z, v.w};
                #pragma unroll
                for (int j = 0; j < 4; j++) {
                    uint32_t hi = f2tf32(vv[j]);
                    float lo = vv[j] - __uint_as_float(hi);
                    As_hi[r * AS_STRIDE + kc + i * 4 + j] = hi;
                    As_lo[r * AS_STRIDE + kc + i * 4 + j] = f2tf32(lo);
                }
            }
            int kk = tid >> 2, jc = (tid & 3) * 16;
            const float4* w4 = (const float4*)(W + kk * 64 + jc);
            #pragma unroll
            for (int i = 0; i < 4; i++) {
                float4 v = w4[i];
                float vv[4] = {v.x, v.y, v.z, v.w};
                #pragma unroll
                for (int j = 0; j < 4; j++) {
                    uint32_t hi = f2tf32(vv[j]);
                    float lo = vv[j] - __uint_as_float(hi);
                    Ws_hi[kk * WS_STRIDE + jc + i * 4 + j] = hi;
                    Ws_lo[kk * WS_STRIDE + jc + i * 4 + j] = f2tf32(lo);
                }
            }
        }
        __syncthreads();
        #pragma unroll
        for (int ks = 0; ks < 8; ks++) {
            int kk = ks * 8;
            int ra = (rbase + g) * AS_STRIDE + kk + t;
            int rb = (rbase + g + 8) * AS_STRIDE + kk + t;
            uint32_t ah0 = As_hi[ra], ah1 = As_hi[rb], ah2 = As_hi[ra + 4], ah3 = As_hi[rb + 4];
            uint32_t al0 = As_lo[ra], al1 = As_lo[rb], al2 = As_lo[ra + 4], al3 = As_lo[rb + 4];
            #pragma unroll
            for (int nt = 0; nt < 4; nt++) {
                int nb = nbase0 + nt * 8 + g;
                int i0 = (kk + t) * WS_STRIDE + nb;
                int i1 = (kk + t + 4) * WS_STRIDE + nb;
                uint32_t bh0 = Ws_hi[i0], bh1 = Ws_hi[i1];
                uint32_t bl0 = Ws_lo[i0], bl1 = Ws_lo[i1];
                mma_tf32(acc[nt], al0, al1, al2, al3, bh0, bh1);
                mma_tf32(acc[nt], ah0, ah1, ah2, ah3, bl0, bl1);
                mma_tf32(acc[nt], ah0, ah1, ah2, ah3, bh0, bh1);
            }
        }
    }
}

// layer 1: h1 = relu(x@W1_root + agg@W1_agg + b1)
__global__ void k_gemm_tc(const float* __restrict__ A0, const float* __restrict__ W0,
                          const float* __restrict__ W1, const float* __restrict__ bias, int n)
{
    float acc[4][4] = {};
    gemm_mainloop(A0, W0, W1, n, acc);

    int lane = threadIdx.x & 31, wid = threadIdx.x >> 5;
    int row0 = blockIdx.x * 64;
    int rbase = (wid >> 1) * 16, nbase0 = (wid & 1) * 32;
    int g = lane >> 2, t = lane & 3;
    #pragma unroll
    for (int nt = 0; nt < 4; nt++) {
        int col = nbase0 + nt * 8 + 2 * t;
        float b0v = bias[col], b1v = bias[col + 1];
        int r_top = row0 + rbase + g;
        if (r_top < n) {
            float2 o;
            o.x = fmaxf(acc[nt][0] + b0v, 0.f);
            o.y = fmaxf(acc[nt][1] + b1v, 0.f);
            *(float2*)(g_h1 + (size_t)r_top * 64 + col) = o;
        }
        int r_bot = r_top + 8;
        if (r_bot < n) {
            float2 o;
            o.x = fmaxf(acc[nt][2] + b0v, 0.f);
            o.y = fmaxf(acc[nt][3] + b1v, 0.f);
            *(float2*)(g_h1 + (size_t)r_bot * 64 + col) = o;
        }
    }
}

// layer 2 + fused 64->2 head: out = relu(h1@W2_root + agg@W2_agg + b2) @ Wlin + blin
__global__ void k_gemm_tc_final(const float* __restrict__ W0, const float* __restrict__ W1,
                                const float* __restrict__ bias,
                                const float* __restrict__ Wlin, const float* __restrict__ blin,
                                float* __restrict__ out, int n)
{
    __shared__ float Wls[128];
    __shared__ float bls[2];
    int tid = threadIdx.x;
    if (tid < 128) Wls[tid] = Wlin[tid];
    if (tid < 2)   bls[tid] = blin[tid];

    float acc[4][4] = {};
    gemm_mainloop((const float*)g_h1, W0, W1, n, acc);

    int lane = tid & 31, wid = tid >> 5;
    int row0 = blockIdx.x * 64;
    int rbase = (wid >> 1) * 16, nbase0 = (wid & 1) * 32;
    int g = lane >> 2, t = lane & 3;

    float* Hs = (float*)dyn_smem;   // reuse As_hi region as Hs[64][AS_STRIDE]
    __syncthreads();                // all mma reads of shared done
    #pragma unroll
    for (int nt = 0; nt < 4; nt++) {
        int col = nbase0 + nt * 8 + 2 * t;
        float b0v = bias[col], b1v = bias[col + 1];
        int rt = rbase + g, rb = rt + 8;
        Hs[rt * AS_STRIDE + col]     = fmaxf(acc[nt][0] + b0v, 0.f);
        Hs[rt * AS_STRIDE + col + 1] = fmaxf(acc[nt][1] + b1v, 0.f);
        Hs[rb * AS_STRIDE + col]     = fmaxf(acc[nt][2] + b0v, 0.f);
        Hs[rb * AS_STRIDE + col + 1] = fmaxf(acc[nt][3] + b1v, 0.f);
    }
    __syncthreads();
    if (tid < 128) {
        int r = tid >> 1, j = tid & 1;
        int gr = row0 + r;
        if (gr < n) {
            float s = bls[j];
            #pragma unroll 8
            for (int c = 0; c < 64; c++)
                s += Hs[r * AS_STRIDE + c] * Wls[c * 2 + j];
            out[(size_t)gr * 2 + j] = s;
        }
    }
}

// ------------------------------ launch -------------------------------------
extern "C" void kernel_launch(void* const* d_in, const int* in_sizes, int n_in,
                              void* d_out, int out_size)
{
    const float* x      = (const float*)d_in[0];
    const void*  ei     = d_in[1];
    const float* W1_agg = (const float*)d_in[2];
    const float* W1_root= (const float*)d_in[3];
    const float* b1     = (const float*)d_in[4];
    const float* W2_agg = (const float*)d_in[5];
    const float* W2_root= (const float*)d_in[6];
    const float* b2     = (const float*)d_in[7];
    const float* W_lin  = (const float*)d_in[8];
    const float* b_lin  = (const float*)d_in[9];
    float*       out    = (float*)d_out;

    int n = in_sizes[0] / F;       // 100000
    int E = in_sizes[1] / 2;       // 1600000
    int nb = (n + SCAN_EPB - 1) / SCAN_EPB;

    static int attr_done = 0;
    if (!attr_done) {
        cudaFuncSetAttribute(k_gemm_tc, cudaFuncAttributeMaxDynamicSharedMemorySize, GEMM_SMEM);
        cudaFuncSetAttribute(k_gemm_tc_final, cudaFuncAttributeMaxDynamicSharedMemorySize, GEMM_SMEM);
        attr_done = 1;
    }

    // CSR build (reused by both layers)
    k_zero_detect<<<(n + 255) / 256, 256>>>(ei, n);
    k_count<<<(E + 255) / 256, 256>>>(ei, E, n);
    k_scan_bsum<<<nb, SCAN_TPB>>>(n);
    k_scan_bscan<<<1, 32>>>(nb);
    k_scan_final<<<nb, SCAN_TPB>>>(n);
    k_fill<<<(E + 255) / 256, 256>>>(ei, E, n);

    int agg_blocks = (n * 32 + 255) / 256;
    int gemm_blocks = (n + 63) / 64;

    // layer 1
    k_agg_x<<<agg_blocks, 256>>>(x, n);
    k_gemm_tc<<<gemm_blocks, 256, GEMM_SMEM>>>(x, W1_root, W1_agg, b1, n);
    // layer 2 + fused output head
    k_agg_h1<<<agg_blocks, 256>>>(n);
    k_gemm_tc_final<<<gemm_blocks, 256, GEMM_SMEM>>>(W2_root, W2_agg, b2, W_lin, b_lin, out, n);
}